// round 14
// baseline (speedup 1.0000x reference)
#include <cuda_runtime.h>
#include <cuda_bf16.h>
#include <cstdint>

#define NN 200000
#define NE 600000
#define NGR 4000
#define EMB 128
#define NL 5

// ------------- device scratch (static; no allocation anywhere) -------------
__device__ unsigned g_hsplit[(size_t)NN * 128];   // interleaved {bf16hi, bf16lo} per col-pair
__device__ float g_h[(size_t)NN * EMB];           // fp32 h, final layer only (for pool)
__device__ float g_xl[(size_t)NN * EMB];
__device__ float g_norm[NE];
__device__ float g_deg[NN];
__device__ int   g_degc[NN];
__device__ int   g_cnt[NN];
__device__ int   g_fill[NN];
__device__ int   g_rowptr[NN + 1];
__device__ uint2 g_epack[NE];                     // {src | code<<18, norm} in CSR order
__device__ int   g_scanbuf[NN];
__device__ int   g_bsums[256];
__device__ int   g_gcnt[NGR];
__device__ int   g_gptr[NGR + 1];
__device__ unsigned g_WfHi[NL * 8 * 16 * 32 * 2];
__device__ unsigned g_WfLo[NL * 8 * 16 * 32 * 2];
__device__ float g_b01[NL * 64 * EMB];            // merged bond0+bond1 table
__device__ float g_bnsc[NL * EMB];
__device__ float g_bnsh[NL * EMB];

// ------------- helpers -------------
__device__ __forceinline__ void bfsplit(float2 v, unsigned& hi, unsigned& lo) {
    __nv_bfloat16 hx = __float2bfloat16(v.x), hy = __float2bfloat16(v.y);
    __nv_bfloat162 hp; hp.x = hx; hp.y = hy;
    hi = *reinterpret_cast<unsigned*>(&hp);
    __nv_bfloat162 lp;
    lp.x = __float2bfloat16(v.x - __bfloat162float(hx));
    lp.y = __float2bfloat16(v.y - __bfloat162float(hy));
    lo = *reinterpret_cast<unsigned*>(&lp);
}

#define MMA(d, a, b0_, b1_)                                                    \
    asm volatile(                                                              \
        "mma.sync.aligned.m16n8k16.row.col.f32.bf16.bf16.f32 "                 \
        "{%0,%1,%2,%3}, {%4,%5,%6,%7}, {%8,%9}, {%0,%1,%2,%3};"                \
        : "+f"((d)[0]), "+f"((d)[1]), "+f"((d)[2]), "+f"((d)[3])               \
        : "r"((a)[0]), "r"((a)[1]), "r"((a)[2]), "r"((a)[3]),                  \
          "r"(b0_), "r"(b1_))

// ------------- setup -------------
__global__ void k_zero() {
    int i = blockIdx.x * blockDim.x + threadIdx.x;
    if (i < NN) { g_degc[i] = 0; g_cnt[i] = 0; g_fill[i] = 0; }
    if (i < NGR) g_gcnt[i] = 0;
}

__global__ void k_hist(const int* __restrict__ ei, const int* __restrict__ batch) {
    int i = blockIdx.x * blockDim.x + threadIdx.x;
    if (i < NE) {
        atomicAdd(&g_degc[ei[i]], 1);       // src histogram -> degree
        atomicAdd(&g_cnt[ei[NE + i]], 1);   // dst histogram -> CSR counts
    }
    if (i < NN) atomicAdd(&g_gcnt[batch[i]], 1);
}

__global__ void k_degnorm(const int* __restrict__ ei) {
    int i = blockIdx.x * blockDim.x + threadIdx.x;
    if (i < NN) g_deg[i] = (float)g_degc[i] + 1.0f;
    if (i < NE) {
        int s = ei[i], d = ei[NE + i];
        g_norm[i] = rsqrtf((float)g_degc[s] + 1.0f) * rsqrtf((float)g_degc[d] + 1.0f);
    }
}

__global__ void k_scan1() {
    __shared__ int s[1024];
    int i = blockIdx.x * 1024 + threadIdx.x;
    int v = (i < NN) ? g_cnt[i] : 0;
    s[threadIdx.x] = v;
    __syncthreads();
    for (int d = 1; d < 1024; d <<= 1) {
        int t = (threadIdx.x >= d) ? s[threadIdx.x - d] : 0;
        __syncthreads();
        s[threadIdx.x] += t;
        __syncthreads();
    }
    if (i < NN) g_scanbuf[i] = s[threadIdx.x];
    if (threadIdx.x == 1023) g_bsums[blockIdx.x] = s[1023];
}

// block-sum exclusive prefix computed redundantly per block (196 values, trivial)
__global__ void k_scan3() {
    __shared__ int sb[196];
    __shared__ int spre[196];
    int tid = threadIdx.x;
    if (tid < 196) sb[tid] = g_bsums[tid];
    __syncthreads();
    if (tid == 0) {
        int a = 0;
        for (int b = 0; b < 196; b++) { spre[b] = a; a += sb[b]; }
    }
    __syncthreads();
    int i = blockIdx.x * 1024 + tid;
    if (i < NN) {
        int incl = g_scanbuf[i] + spre[blockIdx.x];
        g_rowptr[i] = incl - g_cnt[i];
        if (i == NN - 1) g_rowptr[NN] = incl;
    }
}

// scatter edges into CSR order, writing packed metadata directly
__global__ void k_scatter(const int* __restrict__ ei, const int* __restrict__ eattr) {
    int i = blockIdx.x * blockDim.x + threadIdx.x;
    if (i < NE) {
        int d = ei[NE + i];
        int p = atomicAdd(&g_fill[d], 1);
        int pos = g_rowptr[d] + p;
        unsigned src = (unsigned)ei[i];
        unsigned code = (unsigned)(eattr[i * 3] | (eattr[i * 3 + 1] << 3) |
                                   (eattr[i * 3 + 2] << 6));
        g_epack[pos] = make_uint2(src | (code << 18), __float_as_uint(g_norm[i]));
    }
}

// single-block scan for graph segments (only needed before poolhead)
__global__ void k_gscan() {
    __shared__ int s[1024];
    __shared__ int carry;
    int tid = threadIdx.x;
    if (tid == 0) carry = 0;
    __syncthreads();
    for (int ch = 0; ch < 4; ch++) {
        int i = ch * 1024 + tid;
        int v = (i < NGR) ? g_gcnt[i] : 0;
        s[tid] = v;
        __syncthreads();
        for (int d = 1; d < 1024; d <<= 1) {
            int t = (tid >= d) ? s[tid - d] : 0;
            __syncthreads();
            s[tid] += t;
            __syncthreads();
        }
        int incl = s[tid] + carry;
        if (i < NGR) g_gptr[i] = incl - v;
        if (i == NGR - 1) g_gptr[NGR] = incl;
        __syncthreads();
        if (tid == 0) carry += s[1023];
        __syncthreads();
    }
}

// bn prep + W fragment pre-split + merged bond0+bond1 table
__global__ void k_prep(const float* __restrict__ W, const float* __restrict__ bond,
                       const float* __restrict__ mean, const float* __restrict__ var,
                       const float* __restrict__ gamma, const float* __restrict__ beta) {
    int idx = blockIdx.x * blockDim.x + threadIdx.x;
    if (idx < NL * EMB) {
        float sc = gamma[idx] * rsqrtf(var[idx] + 1e-5f);
        g_bnsc[idx] = sc;
        g_bnsh[idx] = beta[idx] - mean[idx] * sc;
    }
    if (idx < NL * 8 * 16 * 32 * 2) {
        int r = idx & 1, lane = (idx >> 1) & 31, nt = (idx >> 6) & 15,
            kt = (idx >> 10) & 7, l = idx >> 13;
        int gid = lane >> 2, tig = lane & 3;
        int k0 = kt * 16 + tig * 2 + r * 8;
        int n = nt * 8 + gid;
        float w0 = W[(l * EMB + k0) * EMB + n];
        float w1 = W[(l * EMB + k0 + 1) * EMB + n];
        unsigned hi, lo;
        bfsplit(make_float2(w0, w1), hi, lo);
        g_WfHi[idx] = hi;
        g_WfLo[idx] = lo;
    }
    if (idx < NL * 64 * EMB) {
        // merged table: g_b01[l][a1*8+a0][c] = bond[l,0,a0,c] + bond[l,1,a1,c]
        int l = idx >> 13, rem = idx & 8191;
        int row = rem >> 7, c = rem & 127;
        int a0 = row & 7, a1 = row >> 3;
        g_b01[idx] = bond[l * 3 * 8 * EMB + a0 * EMB + c] +
                     bond[l * 3 * 8 * EMB + (8 + a1) * EMB + c];
    }
}

// ------------- atom encoder -> bf16 hi/lo split h -------------
__global__ void __launch_bounds__(256) k_enc(const int* __restrict__ x,
                                             const float* __restrict__ aemb) {
    int tid = threadIdx.x, wid = tid >> 5, lane = tid & 31;
    int n = blockIdx.x * 8 + wid;
    if (n >= NN) return;
    int c = lane * 4;
    float4 acc = make_float4(0.f, 0.f, 0.f, 0.f);
#pragma unroll
    for (int f = 0; f < 9; f++) {
        int v = x[n * 9 + f];
        float4 t = *(const float4*)(aemb + ((size_t)(f * 64 + v)) * EMB + c);
        acc.x += t.x; acc.y += t.y; acc.z += t.z; acc.w += t.w;
    }
    uint4 o;
    bfsplit(make_float2(acc.x, acc.y), o.x, o.y);
    bfsplit(make_float2(acc.z, acc.w), o.z, o.w);
    *(uint4*)(g_hsplit + (size_t)n * 128 + c) = o;
}

// ------------- GEMM: xl = h @ W[l] + b[l], bf16 3-pass split (A pre-split) -------------
// 256 rows/block, 2 sequential 128-row sub-tiles. N-split across warps: warp w owns
// m-pair (w&3, 32 rows) x nt-half (w>>2, 8 n-tiles) -> each B fragment read feeds 6 MMAs.
__global__ void __launch_bounds__(256) k_gemm(int layer, const float* __restrict__ bias) {
    extern __shared__ unsigned sm[];
    unsigned* sBhi = sm;            // 8192 words
    unsigned* sBlo = sm + 8192;     // 8192 words
    float* sbias = (float*)(sm + 16384);
    int tid = threadIdx.x;
    {
        const uint4* srcH = (const uint4*)(g_WfHi + layer * 8192);
        const uint4* srcL = (const uint4*)(g_WfLo + layer * 8192);
        uint4* dH = (uint4*)sBhi;
        uint4* dL = (uint4*)sBlo;
#pragma unroll
        for (int i = 0; i < 8; i++) {
            dH[tid + i * 256] = srcH[tid + i * 256];
            dL[tid + i * 256] = srcL[tid + i * 256];
        }
        if (tid < EMB) sbias[tid] = bias[layer * EMB + tid];
    }
    __syncthreads();

    int wid = tid >> 5, lane = tid & 31, gid = lane >> 2, tig = lane & 3;
    int wm = wid & 3, wn = wid >> 2;    // m-pair, nt-half
    const uint2* hs = (const uint2*)g_hsplit;
    const uint2 z2 = make_uint2(0u, 0u);

#pragma unroll 1
    for (int sub = 0; sub < 2; sub++) {
        long base = (long)blockIdx.x * 256 + sub * 128 + wm * 32;
        long r0 = base + gid, r1 = r0 + 8, r2 = r0 + 16, r3 = r0 + 24;
        bool ok0 = r0 < NN, ok1 = r1 < NN, ok2 = r2 < NN, ok3 = r3 < NN;
        float acc0[8][4], acc1[8][4];
#pragma unroll
        for (int nt = 0; nt < 8; nt++) {
            acc0[nt][0] = 0.f; acc0[nt][1] = 0.f; acc0[nt][2] = 0.f; acc0[nt][3] = 0.f;
            acc1[nt][0] = 0.f; acc1[nt][1] = 0.f; acc1[nt][2] = 0.f; acc1[nt][3] = 0.f;
        }

#pragma unroll 2
        for (int kt = 0; kt < 8; kt++) {
            int kw = kt * 8 + tig;
            uint2 a00 = ok0 ? hs[r0 * 64 + kw]     : z2;
            uint2 a10 = ok1 ? hs[r1 * 64 + kw]     : z2;
            uint2 a01 = ok0 ? hs[r0 * 64 + kw + 4] : z2;
            uint2 a11 = ok1 ? hs[r1 * 64 + kw + 4] : z2;
            uint2 a20 = ok2 ? hs[r2 * 64 + kw]     : z2;
            uint2 a30 = ok3 ? hs[r3 * 64 + kw]     : z2;
            uint2 a21 = ok2 ? hs[r2 * 64 + kw + 4] : z2;
            uint2 a31 = ok3 ? hs[r3 * 64 + kw + 4] : z2;
            unsigned aH0[4] = {a00.x, a10.x, a01.x, a11.x};
            unsigned aL0[4] = {a00.y, a10.y, a01.y, a11.y};
            unsigned aH1[4] = {a20.x, a30.x, a21.x, a31.x};
            unsigned aL1[4] = {a20.y, a30.y, a21.y, a31.y};
            const uint2* BH = ((const uint2*)sBhi) + (kt * 16 + wn * 8) * 32 + lane;
            const uint2* BL = ((const uint2*)sBlo) + (kt * 16 + wn * 8) * 32 + lane;
#pragma unroll
            for (int nt = 0; nt < 8; nt++) {
                uint2 bh = BH[nt * 32];
                uint2 bl = BL[nt * 32];
                MMA(acc0[nt], aH0, bh.x, bh.y);
                MMA(acc0[nt], aH0, bl.x, bl.y);
                MMA(acc0[nt], aL0, bh.x, bh.y);
                MMA(acc1[nt], aH1, bh.x, bh.y);
                MMA(acc1[nt], aH1, bl.x, bl.y);
                MMA(acc1[nt], aL1, bh.x, bh.y);
            }
        }

#pragma unroll
        for (int nt = 0; nt < 8; nt++) {
            int c = (wn * 8 + nt) * 8 + tig * 2;
            float b0 = sbias[c], b1 = sbias[c + 1];
            if (ok0) *(float2*)(g_xl + r0 * EMB + c) =
                make_float2(acc0[nt][0] + b0, acc0[nt][1] + b1);
            if (ok1) *(float2*)(g_xl + r1 * EMB + c) =
                make_float2(acc0[nt][2] + b0, acc0[nt][3] + b1);
            if (ok2) *(float2*)(g_xl + r2 * EMB + c) =
                make_float2(acc1[nt][0] + b0, acc1[nt][1] + b1);
            if (ok3) *(float2*)(g_xl + r3 * EMB + c) =
                make_float2(acc1[nt][2] + b0, acc1[nt][3] + b1);
        }
    }
}

// ------------- aggregation + self loop + BN (+relu), warp per node -------------
// R13 structure: merged bond table, __ldg tables, no smem.
__global__ void __launch_bounds__(256) k_agg(int layer, int last,
                                             const float* __restrict__ bond,
                                             const float* __restrict__ root) {
    int tid = threadIdx.x;
    int wid = tid >> 5, lane = tid & 31;
    int n = blockIdx.x * 8 + wid;       // 25000*8 == NN exactly
    int c = lane * 4;

    const float* gm = g_b01 + layer * 64 * EMB;          // merged b0+b1 table
    const float* g2 = bond + layer * 3 * 8 * EMB + 16 * EMB;  // b2 table

    float4 x = *(const float4*)(g_xl + (size_t)n * EMB + c);
    float4 rt = __ldg((const float4*)(root + layer * EMB + c));
    float di = 1.0f / g_deg[n];
    float4 acc;
    acc.x = fmaxf(x.x + rt.x, 0.f) * di;
    acc.y = fmaxf(x.y + rt.y, 0.f) * di;
    acc.z = fmaxf(x.z + rt.z, 0.f) * di;
    acc.w = fmaxf(x.w + rt.w, 0.f) * di;

    int p = g_rowptr[n], e = g_rowptr[n + 1];
    for (; p + 1 < e; p += 2) {
        uint2 m0 = g_epack[p], m1 = g_epack[p + 1];
        int s0 = m0.x & 0x3FFFF, s1 = m1.x & 0x3FFFF;
        unsigned c0 = m0.x >> 18, c1 = m1.x >> 18;
        float n0 = __uint_as_float(m0.y), n1 = __uint_as_float(m1.y);
        float4 r0 = *(const float4*)(g_xl + (size_t)s0 * EMB + c);
        float4 r1 = *(const float4*)(g_xl + (size_t)s1 * EMB + c);
        float4 ba = __ldg((const float4*)(gm + (c0 & 63) * EMB + c));
        float4 bb = __ldg((const float4*)(g2 + (c0 >> 6) * EMB + c));
        float4 bc = __ldg((const float4*)(gm + (c1 & 63) * EMB + c));
        float4 bd = __ldg((const float4*)(g2 + (c1 >> 6) * EMB + c));
        acc.x += n0 * fmaxf(r0.x + ba.x + bb.x, 0.f) + n1 * fmaxf(r1.x + bc.x + bd.x, 0.f);
        acc.y += n0 * fmaxf(r0.y + ba.y + bb.y, 0.f) + n1 * fmaxf(r1.y + bc.y + bd.y, 0.f);
        acc.z += n0 * fmaxf(r0.z + ba.z + bb.z, 0.f) + n1 * fmaxf(r1.z + bc.z + bd.z, 0.f);
        acc.w += n0 * fmaxf(r0.w + ba.w + bb.w, 0.f) + n1 * fmaxf(r1.w + bc.w + bd.w, 0.f);
    }
    if (p < e) {
        uint2 m0 = g_epack[p];
        int s0 = m0.x & 0x3FFFF;
        unsigned c0 = m0.x >> 18;
        float n0 = __uint_as_float(m0.y);
        float4 r0 = *(const float4*)(g_xl + (size_t)s0 * EMB + c);
        float4 ba = __ldg((const float4*)(gm + (c0 & 63) * EMB + c));
        float4 bb = __ldg((const float4*)(g2 + (c0 >> 6) * EMB + c));
        acc.x += n0 * fmaxf(r0.x + ba.x + bb.x, 0.f);
        acc.y += n0 * fmaxf(r0.y + ba.y + bb.y, 0.f);
        acc.z += n0 * fmaxf(r0.z + ba.z + bb.z, 0.f);
        acc.w += n0 * fmaxf(r0.w + ba.w + bb.w, 0.f);
    }

    float4 sc = __ldg((const float4*)(g_bnsc + layer * EMB + c));
    float4 sh = __ldg((const float4*)(g_bnsh + layer * EMB + c));
    float4 o;
    o.x = acc.x * sc.x + sh.x;
    o.y = acc.y * sc.y + sh.y;
    o.z = acc.z * sc.z + sh.z;
    o.w = acc.w * sc.w + sh.w;
    if (!last) {
        o.x = fmaxf(o.x, 0.f); o.y = fmaxf(o.y, 0.f);
        o.z = fmaxf(o.z, 0.f); o.w = fmaxf(o.w, 0.f);
        uint4 u;
        bfsplit(make_float2(o.x, o.y), u.x, u.y);
        bfsplit(make_float2(o.z, o.w), u.z, u.w);
        *(uint4*)(g_hsplit + (size_t)n * 128 + c) = u;
    } else {
        *(float4*)(g_h + (size_t)n * EMB + c) = o;
    }
}

// ------------- fused pool + head: 8 graphs per block -------------
__global__ void __launch_bounds__(128) k_poolhead(const float* __restrict__ hw,
                                                  const float* __restrict__ hb,
                                                  float* __restrict__ out) {
    __shared__ float sh[8][EMB];
    int t = threadIdx.x;
    int g0 = blockIdx.x * 8;
#pragma unroll
    for (int j = 0; j < 8; j++) {
        int g = g0 + j;
        float a = 0.f;
        int s = g_gptr[g], e = g_gptr[g + 1];
        for (int n = s; n < e; n++) a += g_h[(size_t)n * EMB + t];
        sh[j][t] = a;
    }
    __syncthreads();
    float o[8];
    float bv = hb[t];
#pragma unroll
    for (int j = 0; j < 8; j++) o[j] = bv;
#pragma unroll 8
    for (int cc = 0; cc < EMB; cc++) {
        float w = hw[cc * 128 + t];
#pragma unroll
        for (int j = 0; j < 8; j++) o[j] += sh[j][cc] * w;
    }
#pragma unroll
    for (int j = 0; j < 8; j++) out[(g0 + j) * 128 + t] = o[j];
}

// ------------- launch -------------
extern "C" void kernel_launch(void* const* d_in, const int* in_sizes, int n_in,
                              void* d_out, int out_size) {
    const int* x      = (const int*)d_in[0];
    const int* ei     = (const int*)d_in[1];
    const int* eattr  = (const int*)d_in[2];
    const int* batch  = (const int*)d_in[3];
    const float* aemb = (const float*)d_in[4];
    const float* bemb = (const float*)d_in[5];
    const float* W    = (const float*)d_in[6];
    const float* bb   = (const float*)d_in[7];
    const float* root = (const float*)d_in[8];
    const float* bnm  = (const float*)d_in[9];
    const float* bnv  = (const float*)d_in[10];
    const float* bng  = (const float*)d_in[11];
    const float* bnb  = (const float*)d_in[12];
    const float* hw   = (const float*)d_in[13];
    const float* hb   = (const float*)d_in[14];
    float* out = (float*)d_out;

    cudaFuncSetAttribute(k_gemm, cudaFuncAttributeMaxDynamicSharedMemorySize, 66048);

    // Order chosen so the ncu-sampled launch (index 3) is k_gemm layer 0.
    k_enc<<<25000, 256>>>(x, aemb);                     // 0: needs only x, aemb
    k_prep<<<160, 256>>>(W, bemb, bnm, bnv, bng, bnb);  // 1: needs only params
    k_zero<<<(NN + 255) / 256, 256>>>();                // 2
    k_gemm<<<782, 256, 66048>>>(0, bb);                 // 3: needs enc + prep
    k_hist<<<(NE + 255) / 256, 256>>>(ei, batch);       // 4
    k_degnorm<<<(NE + 255) / 256, 256>>>(ei);           // 5
    k_scan1<<<196, 1024>>>();                           // 6
    k_scan3<<<196, 1024>>>();                           // 7
    k_scatter<<<(NE + 255) / 256, 256>>>(ei, eattr);    // 8
    k_agg<<<25000, 256>>>(0, 0, bemb, root);            // 9

    for (int l = 1; l < NL; l++) {
        k_gemm<<<782, 256, 66048>>>(l, bb);
        k_agg<<<25000, 256>>>(l, (l == NL - 1) ? 1 : 0, bemb, root);
    }

    k_gscan<<<1, 1024>>>();
    k_poolhead<<<500, 128>>>(hw, hb, out);
}

// round 15
// speedup vs baseline: 1.1219x; 1.1219x over previous
#include <cuda_runtime.h>
#include <cuda_bf16.h>
#include <cstdint>

#define NN 200000
#define NE 600000
#define NGR 4000
#define EMB 128
#define NL 5

// ------------- device scratch (static; no allocation anywhere) -------------
__device__ unsigned g_hsplit[(size_t)NN * 128];   // interleaved {bf16hi, bf16lo} per col-pair
__device__ float g_h[(size_t)NN * EMB];           // fp32 h, final layer only (for pool)
__device__ float g_xl[(size_t)NN * EMB];
__device__ float g_norm[NE];
__device__ float g_deg[NN];
__device__ int   g_degc[NN];
__device__ int   g_cnt[NN];
__device__ int   g_fill[NN];
__device__ int   g_rowptr[NN + 1];
__device__ uint2 g_epack[NE];                     // {src | code<<18, norm} in CSR order
__device__ int   g_scanbuf[NN];
__device__ int   g_bsums[256];
__device__ int   g_gcnt[NGR];
__device__ int   g_gptr[NGR + 1];
__device__ unsigned g_WfHi[NL * 8 * 16 * 32 * 2];
__device__ unsigned g_WfLo[NL * 8 * 16 * 32 * 2];
__device__ float g_b012[NL * 512 * EMB];          // fully merged bond table (code = a2a1a0)
__device__ float g_bnsc[NL * EMB];
__device__ float g_bnsh[NL * EMB];

// ------------- helpers -------------
__device__ __forceinline__ void bfsplit(float2 v, unsigned& hi, unsigned& lo) {
    __nv_bfloat16 hx = __float2bfloat16(v.x), hy = __float2bfloat16(v.y);
    __nv_bfloat162 hp; hp.x = hx; hp.y = hy;
    hi = *reinterpret_cast<unsigned*>(&hp);
    __nv_bfloat162 lp;
    lp.x = __float2bfloat16(v.x - __bfloat162float(hx));
    lp.y = __float2bfloat16(v.y - __bfloat162float(hy));
    lo = *reinterpret_cast<unsigned*>(&lp);
}

#define MMA(d, a, b0_, b1_)                                                    \
    asm volatile(                                                              \
        "mma.sync.aligned.m16n8k16.row.col.f32.bf16.bf16.f32 "                 \
        "{%0,%1,%2,%3}, {%4,%5,%6,%7}, {%8,%9}, {%0,%1,%2,%3};"                \
        : "+f"((d)[0]), "+f"((d)[1]), "+f"((d)[2]), "+f"((d)[3])               \
        : "r"((a)[0]), "r"((a)[1]), "r"((a)[2]), "r"((a)[3]),                  \
          "r"(b0_), "r"(b1_))

// ------------- setup -------------
__global__ void k_zero() {
    int i = blockIdx.x * blockDim.x + threadIdx.x;
    if (i < NN) { g_degc[i] = 0; g_cnt[i] = 0; g_fill[i] = 0; }
    if (i < NGR) g_gcnt[i] = 0;
}

__global__ void k_hist(const int* __restrict__ ei, const int* __restrict__ batch) {
    int i = blockIdx.x * blockDim.x + threadIdx.x;
    if (i < NE) {
        atomicAdd(&g_degc[ei[i]], 1);       // src histogram -> degree
        atomicAdd(&g_cnt[ei[NE + i]], 1);   // dst histogram -> CSR counts
    }
    if (i < NN) atomicAdd(&g_gcnt[batch[i]], 1);
}

__global__ void k_degnorm(const int* __restrict__ ei) {
    int i = blockIdx.x * blockDim.x + threadIdx.x;
    if (i < NN) g_deg[i] = (float)g_degc[i] + 1.0f;
    if (i < NE) {
        int s = ei[i], d = ei[NE + i];
        g_norm[i] = rsqrtf((float)g_degc[s] + 1.0f) * rsqrtf((float)g_degc[d] + 1.0f);
    }
}

__global__ void k_scan1() {
    __shared__ int s[1024];
    int i = blockIdx.x * 1024 + threadIdx.x;
    int v = (i < NN) ? g_cnt[i] : 0;
    s[threadIdx.x] = v;
    __syncthreads();
    for (int d = 1; d < 1024; d <<= 1) {
        int t = (threadIdx.x >= d) ? s[threadIdx.x - d] : 0;
        __syncthreads();
        s[threadIdx.x] += t;
        __syncthreads();
    }
    if (i < NN) g_scanbuf[i] = s[threadIdx.x];
    if (threadIdx.x == 1023) g_bsums[blockIdx.x] = s[1023];
}

// block-sum exclusive prefix computed redundantly per block (196 values, trivial)
__global__ void k_scan3() {
    __shared__ int sb[196];
    __shared__ int spre[196];
    int tid = threadIdx.x;
    if (tid < 196) sb[tid] = g_bsums[tid];
    __syncthreads();
    if (tid == 0) {
        int a = 0;
        for (int b = 0; b < 196; b++) { spre[b] = a; a += sb[b]; }
    }
    __syncthreads();
    int i = blockIdx.x * 1024 + tid;
    if (i < NN) {
        int incl = g_scanbuf[i] + spre[blockIdx.x];
        g_rowptr[i] = incl - g_cnt[i];
        if (i == NN - 1) g_rowptr[NN] = incl;
    }
}

// scatter edges into CSR order, writing packed metadata directly
__global__ void k_scatter(const int* __restrict__ ei, const int* __restrict__ eattr) {
    int i = blockIdx.x * blockDim.x + threadIdx.x;
    if (i < NE) {
        int d = ei[NE + i];
        int p = atomicAdd(&g_fill[d], 1);
        int pos = g_rowptr[d] + p;
        unsigned src = (unsigned)ei[i];
        unsigned code = (unsigned)(eattr[i * 3] | (eattr[i * 3 + 1] << 3) |
                                   (eattr[i * 3 + 2] << 6));
        g_epack[pos] = make_uint2(src | (code << 18), __float_as_uint(g_norm[i]));
    }
}

// single-block scan for graph segments (only needed before poolhead)
__global__ void k_gscan() {
    __shared__ int s[1024];
    __shared__ int carry;
    int tid = threadIdx.x;
    if (tid == 0) carry = 0;
    __syncthreads();
    for (int ch = 0; ch < 4; ch++) {
        int i = ch * 1024 + tid;
        int v = (i < NGR) ? g_gcnt[i] : 0;
        s[tid] = v;
        __syncthreads();
        for (int d = 1; d < 1024; d <<= 1) {
            int t = (tid >= d) ? s[tid - d] : 0;
            __syncthreads();
            s[tid] += t;
            __syncthreads();
        }
        int incl = s[tid] + carry;
        if (i < NGR) g_gptr[i] = incl - v;
        if (i == NGR - 1) g_gptr[NGR] = incl;
        __syncthreads();
        if (tid == 0) carry += s[1023];
        __syncthreads();
    }
}

// bn prep + W fragment pre-split + fully merged bond table
__global__ void k_prep(const float* __restrict__ W, const float* __restrict__ bond,
                       const float* __restrict__ mean, const float* __restrict__ var,
                       const float* __restrict__ gamma, const float* __restrict__ beta) {
    int idx = blockIdx.x * blockDim.x + threadIdx.x;
    if (idx < NL * EMB) {
        float sc = gamma[idx] * rsqrtf(var[idx] + 1e-5f);
        g_bnsc[idx] = sc;
        g_bnsh[idx] = beta[idx] - mean[idx] * sc;
    }
    if (idx < NL * 8 * 16 * 32 * 2) {
        int r = idx & 1, lane = (idx >> 1) & 31, nt = (idx >> 6) & 15,
            kt = (idx >> 10) & 7, l = idx >> 13;
        int gid = lane >> 2, tig = lane & 3;
        int k0 = kt * 16 + tig * 2 + r * 8;
        int n = nt * 8 + gid;
        float w0 = W[(l * EMB + k0) * EMB + n];
        float w1 = W[(l * EMB + k0 + 1) * EMB + n];
        unsigned hi, lo;
        bfsplit(make_float2(w0, w1), hi, lo);
        g_WfHi[idx] = hi;
        g_WfLo[idx] = lo;
    }
    // fully merged table: g_b012[l][code][c] = b0[a0][c] + b1[a1][c] + b2[a2][c]
    // code = a0 | a1<<3 | a2<<6 ; NL*512*EMB = 327680 entries
    for (int t = idx; t < NL * 512 * EMB; t += gridDim.x * blockDim.x) {
        int l = t >> 16, rem = t & 65535;
        int row = rem >> 7, c = rem & 127;
        int a0 = row & 7, a1 = (row >> 3) & 7, a2 = row >> 6;
        const float* b = bond + l * 3 * 8 * EMB;
        g_b012[t] = b[a0 * EMB + c] + b[(8 + a1) * EMB + c] + b[(16 + a2) * EMB + c];
    }
}

// ------------- atom encoder -> bf16 hi/lo split h -------------
__global__ void __launch_bounds__(256) k_enc(const int* __restrict__ x,
                                             const float* __restrict__ aemb) {
    int tid = threadIdx.x, wid = tid >> 5, lane = tid & 31;
    int n = blockIdx.x * 8 + wid;
    if (n >= NN) return;
    int c = lane * 4;
    float4 acc = make_float4(0.f, 0.f, 0.f, 0.f);
#pragma unroll
    for (int f = 0; f < 9; f++) {
        int v = x[n * 9 + f];
        float4 t = *(const float4*)(aemb + ((size_t)(f * 64 + v)) * EMB + c);
        acc.x += t.x; acc.y += t.y; acc.z += t.z; acc.w += t.w;
    }
    uint4 o;
    bfsplit(make_float2(acc.x, acc.y), o.x, o.y);
    bfsplit(make_float2(acc.z, acc.w), o.z, o.w);
    *(uint4*)(g_hsplit + (size_t)n * 128 + c) = o;
}

// ------------- GEMM: xl = h @ W[l] + b[l], bf16 3-pass split (A pre-split) -------------
// R13 configuration (known 79us): 256 rows per block, 2 sequential 128-row sub-tiles.
__global__ void __launch_bounds__(256) k_gemm(int layer, const float* __restrict__ bias) {
    extern __shared__ unsigned sm[];
    unsigned* sBhi = sm;            // 8192 words
    unsigned* sBlo = sm + 8192;     // 8192 words
    float* sbias = (float*)(sm + 16384);
    int tid = threadIdx.x;
    {
        const uint4* srcH = (const uint4*)(g_WfHi + layer * 8192);
        const uint4* srcL = (const uint4*)(g_WfLo + layer * 8192);
        uint4* dH = (uint4*)sBhi;
        uint4* dL = (uint4*)sBlo;
#pragma unroll
        for (int i = 0; i < 8; i++) {
            dH[tid + i * 256] = srcH[tid + i * 256];
            dL[tid + i * 256] = srcL[tid + i * 256];
        }
        if (tid < EMB) sbias[tid] = bias[layer * EMB + tid];
    }
    __syncthreads();

    int wid = tid >> 5, lane = tid & 31, gid = lane >> 2, tig = lane & 3;
    const uint2* hs = (const uint2*)g_hsplit;
    const uint2 z2 = make_uint2(0u, 0u);

#pragma unroll 1
    for (int sub = 0; sub < 2; sub++) {
        long base = (long)blockIdx.x * 256 + sub * 128 + wid * 16;
        long r0 = base + gid, r1 = r0 + 8;
        bool ok0 = r0 < NN, ok1 = r1 < NN;
        float acc[16][4];
#pragma unroll
        for (int nt = 0; nt < 16; nt++) {
            acc[nt][0] = 0.f; acc[nt][1] = 0.f; acc[nt][2] = 0.f; acc[nt][3] = 0.f;
        }

#pragma unroll 2
        for (int kt = 0; kt < 8; kt++) {
            int kw = kt * 8 + tig;
            uint2 a00 = ok0 ? hs[r0 * 64 + kw]     : z2;
            uint2 a10 = ok1 ? hs[r1 * 64 + kw]     : z2;
            uint2 a01 = ok0 ? hs[r0 * 64 + kw + 4] : z2;
            uint2 a11 = ok1 ? hs[r1 * 64 + kw + 4] : z2;
            unsigned aH[4] = {a00.x, a10.x, a01.x, a11.x};
            unsigned aL[4] = {a00.y, a10.y, a01.y, a11.y};
            const uint2* BH = ((const uint2*)sBhi) + (kt * 16) * 32 + lane;
            const uint2* BL = ((const uint2*)sBlo) + (kt * 16) * 32 + lane;
#pragma unroll
            for (int nt = 0; nt < 16; nt++) {
                uint2 bh = BH[nt * 32];
                uint2 bl = BL[nt * 32];
                MMA(acc[nt], aH, bh.x, bh.y);
                MMA(acc[nt], aH, bl.x, bl.y);
                MMA(acc[nt], aL, bh.x, bh.y);
            }
        }

#pragma unroll
        for (int nt = 0; nt < 16; nt++) {
            int c = nt * 8 + tig * 2;
            float b0 = sbias[c], b1 = sbias[c + 1];
            if (ok0) *(float2*)(g_xl + r0 * EMB + c) =
                make_float2(acc[nt][0] + b0, acc[nt][1] + b1);
            if (ok1) *(float2*)(g_xl + r1 * EMB + c) =
                make_float2(acc[nt][2] + b0, acc[nt][3] + b1);
        }
    }
}

// ------------- aggregation + self loop + BN (+relu), warp per node -------------
// R13 structure; single fully-merged bond table read per edge.
__global__ void __launch_bounds__(256) k_agg(int layer, int last,
                                             const float* __restrict__ root) {
    int tid = threadIdx.x;
    int wid = tid >> 5, lane = tid & 31;
    int n = blockIdx.x * 8 + wid;       // 25000*8 == NN exactly
    int c = lane * 4;

    const float* gm = g_b012 + layer * 512 * EMB;    // merged b0+b1+b2 table

    float4 x = *(const float4*)(g_xl + (size_t)n * EMB + c);
    float4 rt = __ldg((const float4*)(root + layer * EMB + c));
    float di = 1.0f / g_deg[n];
    float4 acc;
    acc.x = fmaxf(x.x + rt.x, 0.f) * di;
    acc.y = fmaxf(x.y + rt.y, 0.f) * di;
    acc.z = fmaxf(x.z + rt.z, 0.f) * di;
    acc.w = fmaxf(x.w + rt.w, 0.f) * di;

    int p = g_rowptr[n], e = g_rowptr[n + 1];
    for (; p + 1 < e; p += 2) {
        uint2 m0 = g_epack[p], m1 = g_epack[p + 1];
        int s0 = m0.x & 0x3FFFF, s1 = m1.x & 0x3FFFF;
        unsigned c0 = m0.x >> 18, c1 = m1.x >> 18;
        float n0 = __uint_as_float(m0.y), n1 = __uint_as_float(m1.y);
        float4 r0 = *(const float4*)(g_xl + (size_t)s0 * EMB + c);
        float4 r1 = *(const float4*)(g_xl + (size_t)s1 * EMB + c);
        float4 ba = __ldg((const float4*)(gm + c0 * EMB + c));
        float4 bc = __ldg((const float4*)(gm + c1 * EMB + c));
        acc.x += n0 * fmaxf(r0.x + ba.x, 0.f) + n1 * fmaxf(r1.x + bc.x, 0.f);
        acc.y += n0 * fmaxf(r0.y + ba.y, 0.f) + n1 * fmaxf(r1.y + bc.y, 0.f);
        acc.z += n0 * fmaxf(r0.z + ba.z, 0.f) + n1 * fmaxf(r1.z + bc.z, 0.f);
        acc.w += n0 * fmaxf(r0.w + ba.w, 0.f) + n1 * fmaxf(r1.w + bc.w, 0.f);
    }
    if (p < e) {
        uint2 m0 = g_epack[p];
        int s0 = m0.x & 0x3FFFF;
        unsigned c0 = m0.x >> 18;
        float n0 = __uint_as_float(m0.y);
        float4 r0 = *(const float4*)(g_xl + (size_t)s0 * EMB + c);
        float4 ba = __ldg((const float4*)(gm + c0 * EMB + c));
        acc.x += n0 * fmaxf(r0.x + ba.x, 0.f);
        acc.y += n0 * fmaxf(r0.y + ba.y, 0.f);
        acc.z += n0 * fmaxf(r0.z + ba.z, 0.f);
        acc.w += n0 * fmaxf(r0.w + ba.w, 0.f);
    }

    float4 sc = __ldg((const float4*)(g_bnsc + layer * EMB + c));
    float4 sh = __ldg((const float4*)(g_bnsh + layer * EMB + c));
    float4 o;
    o.x = acc.x * sc.x + sh.x;
    o.y = acc.y * sc.y + sh.y;
    o.z = acc.z * sc.z + sh.z;
    o.w = acc.w * sc.w + sh.w;
    if (!last) {
        o.x = fmaxf(o.x, 0.f); o.y = fmaxf(o.y, 0.f);
        o.z = fmaxf(o.z, 0.f); o.w = fmaxf(o.w, 0.f);
        uint4 u;
        bfsplit(make_float2(o.x, o.y), u.x, u.y);
        bfsplit(make_float2(o.z, o.w), u.z, u.w);
        *(uint4*)(g_hsplit + (size_t)n * 128 + c) = u;
    } else {
        *(float4*)(g_h + (size_t)n * EMB + c) = o;
    }
}

// ------------- fused pool + head: 8 graphs per block -------------
__global__ void __launch_bounds__(128) k_poolhead(const float* __restrict__ hw,
                                                  const float* __restrict__ hb,
                                                  float* __restrict__ out) {
    __shared__ float sh[8][EMB];
    int t = threadIdx.x;
    int g0 = blockIdx.x * 8;
#pragma unroll
    for (int j = 0; j < 8; j++) {
        int g = g0 + j;
        float a = 0.f;
        int s = g_gptr[g], e = g_gptr[g + 1];
        for (int n = s; n < e; n++) a += g_h[(size_t)n * EMB + t];
        sh[j][t] = a;
    }
    __syncthreads();
    float o[8];
    float bv = hb[t];
#pragma unroll
    for (int j = 0; j < 8; j++) o[j] = bv;
#pragma unroll 8
    for (int cc = 0; cc < EMB; cc++) {
        float w = hw[cc * 128 + t];
#pragma unroll
        for (int j = 0; j < 8; j++) o[j] += sh[j][cc] * w;
    }
#pragma unroll
    for (int j = 0; j < 8; j++) out[(g0 + j) * 128 + t] = o[j];
}

// ------------- launch -------------
extern "C" void kernel_launch(void* const* d_in, const int* in_sizes, int n_in,
                              void* d_out, int out_size) {
    const int* x      = (const int*)d_in[0];
    const int* ei     = (const int*)d_in[1];
    const int* eattr  = (const int*)d_in[2];
    const int* batch  = (const int*)d_in[3];
    const float* aemb = (const float*)d_in[4];
    const float* bemb = (const float*)d_in[5];
    const float* W    = (const float*)d_in[6];
    const float* bb   = (const float*)d_in[7];
    const float* root = (const float*)d_in[8];
    const float* bnm  = (const float*)d_in[9];
    const float* bnv  = (const float*)d_in[10];
    const float* bng  = (const float*)d_in[11];
    const float* bnb  = (const float*)d_in[12];
    const float* hw   = (const float*)d_in[13];
    const float* hb   = (const float*)d_in[14];
    float* out = (float*)d_out;

    cudaFuncSetAttribute(k_gemm, cudaFuncAttributeMaxDynamicSharedMemorySize, 66048);

    // Order chosen so the ncu-sampled launch (index 3) is k_gemm layer 0.
    k_enc<<<25000, 256>>>(x, aemb);                     // 0: needs only x, aemb
    k_prep<<<160, 256>>>(W, bemb, bnm, bnv, bng, bnb);  // 1: needs only params
    k_zero<<<(NN + 255) / 256, 256>>>();                // 2
    k_gemm<<<782, 256, 66048>>>(0, bb);                 // 3: needs enc + prep
    k_hist<<<(NE + 255) / 256, 256>>>(ei, batch);       // 4
    k_degnorm<<<(NE + 255) / 256, 256>>>(ei);           // 5
    k_scan1<<<196, 1024>>>();                           // 6
    k_scan3<<<196, 1024>>>();                           // 7
    k_scatter<<<(NE + 255) / 256, 256>>>(ei, eattr);    // 8
    k_agg<<<25000, 256>>>(0, 0, root);                  // 9

    for (int l = 1; l < NL; l++) {
        k_gemm<<<782, 256, 66048>>>(l, bb);
        k_agg<<<25000, 256>>>(l, (l == NL - 1) ? 1 : 0, root);
    }

    k_gscan<<<1, 1024>>>();
    k_poolhead<<<500, 128>>>(hw, hb, out);
}

// round 16
// speedup vs baseline: 1.2093x; 1.0779x over previous
#include <cuda_runtime.h>
#include <cuda_bf16.h>
#include <cuda_fp16.h>
#include <cstdint>

#define NN 200000
#define NE 600000
#define NGR 4000
#define EMB 128
#define NL 5

// ------------- device scratch (static; no allocation anywhere) -------------
__device__ unsigned g_hsplit[(size_t)NN * 128];   // interleaved {bf16hi, bf16lo} per col-pair
__device__ float g_h[(size_t)NN * EMB];           // fp32 h, final layer only (for pool)
__device__ float g_xl[(size_t)NN * EMB];
__device__ float g_norm[NE];
__device__ float g_deg[NN];
__device__ int   g_degc[NN];
__device__ int   g_cnt[NN];
__device__ int   g_fill[NN];
__device__ int   g_rowptr[NN + 1];
__device__ uint2 g_epack[NE];                     // {src | code<<18, norm} in CSR order
__device__ int   g_scanbuf[NN];
__device__ int   g_bsums[256];
__device__ int   g_gcnt[NGR];
__device__ int   g_gptr[NGR + 1];
__device__ unsigned g_WfHi[NL * 8 * 16 * 32 * 2];
__device__ unsigned g_WfLo[NL * 8 * 16 * 32 * 2];
__device__ __half g_b012h[(size_t)NL * 512 * EMB]; // fully merged bond table, fp16
__device__ float g_bnsc[NL * EMB];
__device__ float g_bnsh[NL * EMB];

// ------------- helpers -------------
__device__ __forceinline__ void bfsplit(float2 v, unsigned& hi, unsigned& lo) {
    __nv_bfloat16 hx = __float2bfloat16(v.x), hy = __float2bfloat16(v.y);
    __nv_bfloat162 hp; hp.x = hx; hp.y = hy;
    hi = *reinterpret_cast<unsigned*>(&hp);
    __nv_bfloat162 lp;
    lp.x = __float2bfloat16(v.x - __bfloat162float(hx));
    lp.y = __float2bfloat16(v.y - __bfloat162float(hy));
    lo = *reinterpret_cast<unsigned*>(&lp);
}

#define MMA(d, a, b0_, b1_)                                                    \
    asm volatile(                                                              \
        "mma.sync.aligned.m16n8k16.row.col.f32.bf16.bf16.f32 "                 \
        "{%0,%1,%2,%3}, {%4,%5,%6,%7}, {%8,%9}, {%0,%1,%2,%3};"                \
        : "+f"((d)[0]), "+f"((d)[1]), "+f"((d)[2]), "+f"((d)[3])               \
        : "r"((a)[0]), "r"((a)[1]), "r"((a)[2]), "r"((a)[3]),                  \
          "r"(b0_), "r"(b1_))

// ------------- setup -------------
__global__ void k_zero() {
    int i = blockIdx.x * blockDim.x + threadIdx.x;
    if (i < NN) { g_degc[i] = 0; g_cnt[i] = 0; g_fill[i] = 0; }
    if (i < NGR) g_gcnt[i] = 0;
}

__global__ void k_hist(const int* __restrict__ ei, const int* __restrict__ batch) {
    int i = blockIdx.x * blockDim.x + threadIdx.x;
    if (i < NE) {
        atomicAdd(&g_degc[ei[i]], 1);       // src histogram -> degree
        atomicAdd(&g_cnt[ei[NE + i]], 1);   // dst histogram -> CSR counts
    }
    if (i < NN) atomicAdd(&g_gcnt[batch[i]], 1);
}

__global__ void k_degnorm(const int* __restrict__ ei) {
    int i = blockIdx.x * blockDim.x + threadIdx.x;
    if (i < NN) g_deg[i] = (float)g_degc[i] + 1.0f;
    if (i < NE) {
        int s = ei[i], d = ei[NE + i];
        g_norm[i] = rsqrtf((float)g_degc[s] + 1.0f) * rsqrtf((float)g_degc[d] + 1.0f);
    }
}

__global__ void k_scan1() {
    __shared__ int s[1024];
    int i = blockIdx.x * 1024 + threadIdx.x;
    int v = (i < NN) ? g_cnt[i] : 0;
    s[threadIdx.x] = v;
    __syncthreads();
    for (int d = 1; d < 1024; d <<= 1) {
        int t = (threadIdx.x >= d) ? s[threadIdx.x - d] : 0;
        __syncthreads();
        s[threadIdx.x] += t;
        __syncthreads();
    }
    if (i < NN) g_scanbuf[i] = s[threadIdx.x];
    if (threadIdx.x == 1023) g_bsums[blockIdx.x] = s[1023];
}

// block-sum exclusive prefix computed redundantly per block (196 values, trivial)
__global__ void k_scan3() {
    __shared__ int sb[196];
    __shared__ int spre[196];
    int tid = threadIdx.x;
    if (tid < 196) sb[tid] = g_bsums[tid];
    __syncthreads();
    if (tid == 0) {
        int a = 0;
        for (int b = 0; b < 196; b++) { spre[b] = a; a += sb[b]; }
    }
    __syncthreads();
    int i = blockIdx.x * 1024 + tid;
    if (i < NN) {
        int incl = g_scanbuf[i] + spre[blockIdx.x];
        g_rowptr[i] = incl - g_cnt[i];
        if (i == NN - 1) g_rowptr[NN] = incl;
    }
}

// scatter edges into CSR order, writing packed metadata directly
__global__ void k_scatter(const int* __restrict__ ei, const int* __restrict__ eattr) {
    int i = blockIdx.x * blockDim.x + threadIdx.x;
    if (i < NE) {
        int d = ei[NE + i];
        int p = atomicAdd(&g_fill[d], 1);
        int pos = g_rowptr[d] + p;
        unsigned src = (unsigned)ei[i];
        unsigned code = (unsigned)(eattr[i * 3] | (eattr[i * 3 + 1] << 3) |
                                   (eattr[i * 3 + 2] << 6));
        g_epack[pos] = make_uint2(src | (code << 18), __float_as_uint(g_norm[i]));
    }
}

// single-block scan for graph segments (only needed before poolhead)
__global__ void k_gscan() {
    __shared__ int s[1024];
    __shared__ int carry;
    int tid = threadIdx.x;
    if (tid == 0) carry = 0;
    __syncthreads();
    for (int ch = 0; ch < 4; ch++) {
        int i = ch * 1024 + tid;
        int v = (i < NGR) ? g_gcnt[i] : 0;
        s[tid] = v;
        __syncthreads();
        for (int d = 1; d < 1024; d <<= 1) {
            int t = (tid >= d) ? s[tid - d] : 0;
            __syncthreads();
            s[tid] += t;
            __syncthreads();
        }
        int incl = s[tid] + carry;
        if (i < NGR) g_gptr[i] = incl - v;
        if (i == NGR - 1) g_gptr[NGR] = incl;
        __syncthreads();
        if (tid == 0) carry += s[1023];
        __syncthreads();
    }
}

// bn prep + W fragment pre-split + fully merged bond table (fp16)
__global__ void k_prep(const float* __restrict__ W, const float* __restrict__ bond,
                       const float* __restrict__ mean, const float* __restrict__ var,
                       const float* __restrict__ gamma, const float* __restrict__ beta) {
    int idx = blockIdx.x * blockDim.x + threadIdx.x;
    if (idx < NL * EMB) {
        float sc = gamma[idx] * rsqrtf(var[idx] + 1e-5f);
        g_bnsc[idx] = sc;
        g_bnsh[idx] = beta[idx] - mean[idx] * sc;
    }
    if (idx < NL * 8 * 16 * 32 * 2) {
        int r = idx & 1, lane = (idx >> 1) & 31, nt = (idx >> 6) & 15,
            kt = (idx >> 10) & 7, l = idx >> 13;
        int gid = lane >> 2, tig = lane & 3;
        int k0 = kt * 16 + tig * 2 + r * 8;
        int n = nt * 8 + gid;
        float w0 = W[(l * EMB + k0) * EMB + n];
        float w1 = W[(l * EMB + k0 + 1) * EMB + n];
        unsigned hi, lo;
        bfsplit(make_float2(w0, w1), hi, lo);
        g_WfHi[idx] = hi;
        g_WfLo[idx] = lo;
    }
    // fully merged table (fp16): g_b012h[l][code][c] = b0[a0][c] + b1[a1][c] + b2[a2][c]
    // code = a0 | a1<<3 | a2<<6 ; NL*512*EMB = 327680 entries
    for (int t = idx; t < NL * 512 * EMB; t += gridDim.x * blockDim.x) {
        int l = t >> 16, rem = t & 65535;
        int row = rem >> 7, c = rem & 127;
        int a0 = row & 7, a1 = (row >> 3) & 7, a2 = row >> 6;
        const float* b = bond + l * 3 * 8 * EMB;
        g_b012h[t] = __float2half(b[a0 * EMB + c] + b[(8 + a1) * EMB + c] +
                                  b[(16 + a2) * EMB + c]);
    }
}

// ------------- atom encoder -> bf16 hi/lo split h -------------
__global__ void __launch_bounds__(256) k_enc(const int* __restrict__ x,
                                             const float* __restrict__ aemb) {
    int tid = threadIdx.x, wid = tid >> 5, lane = tid & 31;
    int n = blockIdx.x * 8 + wid;
    if (n >= NN) return;
    int c = lane * 4;
    float4 acc = make_float4(0.f, 0.f, 0.f, 0.f);
#pragma unroll
    for (int f = 0; f < 9; f++) {
        int v = x[n * 9 + f];
        float4 t = *(const float4*)(aemb + ((size_t)(f * 64 + v)) * EMB + c);
        acc.x += t.x; acc.y += t.y; acc.z += t.z; acc.w += t.w;
    }
    uint4 o;
    bfsplit(make_float2(acc.x, acc.y), o.x, o.y);
    bfsplit(make_float2(acc.z, acc.w), o.z, o.w);
    *(uint4*)(g_hsplit + (size_t)n * 128 + c) = o;
}

// ------------- GEMM: xl = h @ W[l] + b[l], bf16 3-pass split (A pre-split) -------------
// R13 configuration (known 79us): 256 rows per block, 2 sequential 128-row sub-tiles.
__global__ void __launch_bounds__(256) k_gemm(int layer, const float* __restrict__ bias) {
    extern __shared__ unsigned sm[];
    unsigned* sBhi = sm;            // 8192 words
    unsigned* sBlo = sm + 8192;     // 8192 words
    float* sbias = (float*)(sm + 16384);
    int tid = threadIdx.x;
    {
        const uint4* srcH = (const uint4*)(g_WfHi + layer * 8192);
        const uint4* srcL = (const uint4*)(g_WfLo + layer * 8192);
        uint4* dH = (uint4*)sBhi;
        uint4* dL = (uint4*)sBlo;
#pragma unroll
        for (int i = 0; i < 8; i++) {
            dH[tid + i * 256] = srcH[tid + i * 256];
            dL[tid + i * 256] = srcL[tid + i * 256];
        }
        if (tid < EMB) sbias[tid] = bias[layer * EMB + tid];
    }
    __syncthreads();

    int wid = tid >> 5, lane = tid & 31, gid = lane >> 2, tig = lane & 3;
    const uint2* hs = (const uint2*)g_hsplit;
    const uint2 z2 = make_uint2(0u, 0u);

#pragma unroll 1
    for (int sub = 0; sub < 2; sub++) {
        long base = (long)blockIdx.x * 256 + sub * 128 + wid * 16;
        long r0 = base + gid, r1 = r0 + 8;
        bool ok0 = r0 < NN, ok1 = r1 < NN;
        float acc[16][4];
#pragma unroll
        for (int nt = 0; nt < 16; nt++) {
            acc[nt][0] = 0.f; acc[nt][1] = 0.f; acc[nt][2] = 0.f; acc[nt][3] = 0.f;
        }

#pragma unroll 2
        for (int kt = 0; kt < 8; kt++) {
            int kw = kt * 8 + tig;
            uint2 a00 = ok0 ? hs[r0 * 64 + kw]     : z2;
            uint2 a10 = ok1 ? hs[r1 * 64 + kw]     : z2;
            uint2 a01 = ok0 ? hs[r0 * 64 + kw + 4] : z2;
            uint2 a11 = ok1 ? hs[r1 * 64 + kw + 4] : z2;
            unsigned aH[4] = {a00.x, a10.x, a01.x, a11.x};
            unsigned aL[4] = {a00.y, a10.y, a01.y, a11.y};
            const uint2* BH = ((const uint2*)sBhi) + (kt * 16) * 32 + lane;
            const uint2* BL = ((const uint2*)sBlo) + (kt * 16) * 32 + lane;
#pragma unroll
            for (int nt = 0; nt < 16; nt++) {
                uint2 bh = BH[nt * 32];
                uint2 bl = BL[nt * 32];
                MMA(acc[nt], aH, bh.x, bh.y);
                MMA(acc[nt], aH, bl.x, bl.y);
                MMA(acc[nt], aL, bh.x, bh.y);
            }
        }

#pragma unroll
        for (int nt = 0; nt < 16; nt++) {
            int c = nt * 8 + tig * 2;
            float b0 = sbias[c], b1 = sbias[c + 1];
            if (ok0) *(float2*)(g_xl + r0 * EMB + c) =
                make_float2(acc[nt][0] + b0, acc[nt][1] + b1);
            if (ok1) *(float2*)(g_xl + r1 * EMB + c) =
                make_float2(acc[nt][2] + b0, acc[nt][3] + b1);
        }
    }
}

// ------------- aggregation + self loop + BN (+relu), warp per node -------------
// R15 structure; single merged bond-table read per edge, now fp16 (256B/row, 2 wavefronts).
__global__ void __launch_bounds__(256) k_agg(int layer, int last,
                                             const float* __restrict__ root) {
    int tid = threadIdx.x;
    int wid = tid >> 5, lane = tid & 31;
    int n = blockIdx.x * 8 + wid;       // 25000*8 == NN exactly
    int c = lane * 4;

    const __half* gm = g_b012h + (size_t)layer * 512 * EMB;  // merged b0+b1+b2 (fp16)

    float4 x = *(const float4*)(g_xl + (size_t)n * EMB + c);
    float4 rt = __ldg((const float4*)(root + layer * EMB + c));
    float di = 1.0f / g_deg[n];
    float4 acc;
    acc.x = fmaxf(x.x + rt.x, 0.f) * di;
    acc.y = fmaxf(x.y + rt.y, 0.f) * di;
    acc.z = fmaxf(x.z + rt.z, 0.f) * di;
    acc.w = fmaxf(x.w + rt.w, 0.f) * di;

    int p = g_rowptr[n], e = g_rowptr[n + 1];
    for (; p + 1 < e; p += 2) {
        uint2 m0 = g_epack[p], m1 = g_epack[p + 1];
        int s0 = m0.x & 0x3FFFF, s1 = m1.x & 0x3FFFF;
        unsigned c0 = m0.x >> 18, c1 = m1.x >> 18;
        float n0 = __uint_as_float(m0.y), n1 = __uint_as_float(m1.y);
        float4 r0 = *(const float4*)(g_xl + (size_t)s0 * EMB + c);
        float4 r1 = *(const float4*)(g_xl + (size_t)s1 * EMB + c);
        uint2 t0 = __ldg((const uint2*)(gm + (size_t)c0 * EMB + c));
        uint2 t1 = __ldg((const uint2*)(gm + (size_t)c1 * EMB + c));
        float2 a0 = __half22float2(*(const __half2*)&t0.x);
        float2 a1 = __half22float2(*(const __half2*)&t0.y);
        float2 b0 = __half22float2(*(const __half2*)&t1.x);
        float2 b1 = __half22float2(*(const __half2*)&t1.y);
        acc.x += n0 * fmaxf(r0.x + a0.x, 0.f) + n1 * fmaxf(r1.x + b0.x, 0.f);
        acc.y += n0 * fmaxf(r0.y + a0.y, 0.f) + n1 * fmaxf(r1.y + b0.y, 0.f);
        acc.z += n0 * fmaxf(r0.z + a1.x, 0.f) + n1 * fmaxf(r1.z + b1.x, 0.f);
        acc.w += n0 * fmaxf(r0.w + a1.y, 0.f) + n1 * fmaxf(r1.w + b1.y, 0.f);
    }
    if (p < e) {
        uint2 m0 = g_epack[p];
        int s0 = m0.x & 0x3FFFF;
        unsigned c0 = m0.x >> 18;
        float n0 = __uint_as_float(m0.y);
        float4 r0 = *(const float4*)(g_xl + (size_t)s0 * EMB + c);
        uint2 t0 = __ldg((const uint2*)(gm + (size_t)c0 * EMB + c));
        float2 a0 = __half22float2(*(const __half2*)&t0.x);
        float2 a1 = __half22float2(*(const __half2*)&t0.y);
        acc.x += n0 * fmaxf(r0.x + a0.x, 0.f);
        acc.y += n0 * fmaxf(r0.y + a0.y, 0.f);
        acc.z += n0 * fmaxf(r0.z + a1.x, 0.f);
        acc.w += n0 * fmaxf(r0.w + a1.y, 0.f);
    }

    float4 sc = __ldg((const float4*)(g_bnsc + layer * EMB + c));
    float4 sh = __ldg((const float4*)(g_bnsh + layer * EMB + c));
    float4 o;
    o.x = acc.x * sc.x + sh.x;
    o.y = acc.y * sc.y + sh.y;
    o.z = acc.z * sc.z + sh.z;
    o.w = acc.w * sc.w + sh.w;
    if (!last) {
        o.x = fmaxf(o.x, 0.f); o.y = fmaxf(o.y, 0.f);
        o.z = fmaxf(o.z, 0.f); o.w = fmaxf(o.w, 0.f);
        uint4 u;
        bfsplit(make_float2(o.x, o.y), u.x, u.y);
        bfsplit(make_float2(o.z, o.w), u.z, u.w);
        *(uint4*)(g_hsplit + (size_t)n * 128 + c) = u;
    } else {
        *(float4*)(g_h + (size_t)n * EMB + c) = o;
    }
}

// ------------- fused pool + head: 8 graphs per block -------------
__global__ void __launch_bounds__(128) k_poolhead(const float* __restrict__ hw,
                                                  const float* __restrict__ hb,
                                                  float* __restrict__ out) {
    __shared__ float sh[8][EMB];
    int t = threadIdx.x;
    int g0 = blockIdx.x * 8;
#pragma unroll
    for (int j = 0; j < 8; j++) {
        int g = g0 + j;
        float a = 0.f;
        int s = g_gptr[g], e = g_gptr[g + 1];
        for (int n = s; n < e; n++) a += g_h[(size_t)n * EMB + t];
        sh[j][t] = a;
    }
    __syncthreads();
    float o[8];
    float bv = hb[t];
#pragma unroll
    for (int j = 0; j < 8; j++) o[j] = bv;
#pragma unroll 8
    for (int cc = 0; cc < EMB; cc++) {
        float w = hw[cc * 128 + t];
#pragma unroll
        for (int j = 0; j < 8; j++) o[j] += sh[j][cc] * w;
    }
#pragma unroll
    for (int j = 0; j < 8; j++) out[(g0 + j) * 128 + t] = o[j];
}

// ------------- launch -------------
extern "C" void kernel_launch(void* const* d_in, const int* in_sizes, int n_in,
                              void* d_out, int out_size) {
    const int* x      = (const int*)d_in[0];
    const int* ei     = (const int*)d_in[1];
    const int* eattr  = (const int*)d_in[2];
    const int* batch  = (const int*)d_in[3];
    const float* aemb = (const float*)d_in[4];
    const float* bemb = (const float*)d_in[5];
    const float* W    = (const float*)d_in[6];
    const float* bb   = (const float*)d_in[7];
    const float* root = (const float*)d_in[8];
    const float* bnm  = (const float*)d_in[9];
    const float* bnv  = (const float*)d_in[10];
    const float* bng  = (const float*)d_in[11];
    const float* bnb  = (const float*)d_in[12];
    const float* hw   = (const float*)d_in[13];
    const float* hb   = (const float*)d_in[14];
    float* out = (float*)d_out;

    cudaFuncSetAttribute(k_gemm, cudaFuncAttributeMaxDynamicSharedMemorySize, 66048);

    // Order chosen so the ncu-sampled launch (index 3) is k_gemm layer 0.
    k_enc<<<25000, 256>>>(x, aemb);                     // 0: needs only x, aemb
    k_prep<<<160, 256>>>(W, bemb, bnm, bnv, bng, bnb);  // 1: needs only params
    k_zero<<<(NN + 255) / 256, 256>>>();                // 2
    k_gemm<<<782, 256, 66048>>>(0, bb);                 // 3: needs enc + prep
    k_hist<<<(NE + 255) / 256, 256>>>(ei, batch);       // 4
    k_degnorm<<<(NE + 255) / 256, 256>>>(ei);           // 5
    k_scan1<<<196, 1024>>>();                           // 6
    k_scan3<<<196, 1024>>>();                           // 7
    k_scatter<<<(NE + 255) / 256, 256>>>(ei, eattr);    // 8
    k_agg<<<25000, 256>>>(0, 0, root);                  // 9

    for (int l = 1; l < NL; l++) {
        k_gemm<<<782, 256, 66048>>>(l, bb);
        k_agg<<<25000, 256>>>(l, (l == NL - 1) ? 1 : 0, root);
    }

    k_gscan<<<1, 1024>>>();
    k_poolhead<<<500, 128>>>(hw, hb, out);
}